// round 4
// baseline (speedup 1.0000x reference)
#include <cuda_runtime.h>

#define NSEG 128
#define EDIM 128
#define NHEAD 4
#define WARPS_PER_BLK 8
#define ROWS_PER_WARP 32
#define ROWS_PER_BLK (WARPS_PER_BLK * ROWS_PER_WARP)

__device__ float g_s[NSEG * NHEAD];
__device__ float g_acc[NSEG * NHEAD * EDIM];
__device__ int   g_is64;
__device__ unsigned int g_done;

__global__ void zero_kernel(const int* __restrict__ b32, int N) {
    int i = blockIdx.x * blockDim.x + threadIdx.x;
    if (i < NSEG * NHEAD * EDIM) g_acc[i] = 0.0f;
    if (i < NSEG * NHEAD)        g_s[i]   = 0.0f;
    if (i == 0) {
        g_done = 0;
        // int64 (LE): the int32 view's high words at the tail are zero.
        int a = b32[N - 1];
        int b = (N >= 3) ? b32[N - 3] : 1;
        int c = (N >= 5) ? b32[N - 5] : 1;
        g_is64 = (a == 0 && b == 0 && c == 0) ? 1 : 0;
    }
}

// One row: thinned head reduction (13 SHFL, 1 MUFU). Verified in round 3.
#define ROW_BODY(xv, accS, a0, a1, a2, a3)                                         \
    {                                                                              \
        float p0 = xv.x*wv0.x + xv.y*wv0.y + xv.z*wv0.z + xv.w*wv0.w;              \
        float p1 = xv.x*wv1.x + xv.y*wv1.y + xv.z*wv1.z + xv.w*wv1.w;              \
        float p2 = xv.x*wv2.x + xv.y*wv2.y + xv.z*wv2.z + xv.w*wv2.w;              \
        float p3 = xv.x*wv3.x + xv.y*wv3.y + xv.z*wv3.z + xv.w*wv3.w;              \
        float t0 = (lane & 1) ? p0 : p2;                                           \
        float t1 = (lane & 1) ? p1 : p3;                                           \
        t0 = __shfl_xor_sync(0xffffffffu, t0, 1);                                  \
        t1 = __shfl_xor_sync(0xffffffffu, t1, 1);                                  \
        float u0 = ((lane & 1) ? p2 : p0) + t0;                                    \
        float u1 = ((lane & 1) ? p3 : p1) + t1;                                    \
        float tt = b1v ? u0 : u1;                                                  \
        tt = __shfl_xor_sync(0xffffffffu, tt, 2);                                  \
        float E = (b1v ? u1 : u0) + tt;                                            \
        E += __shfl_xor_sync(0xffffffffu, E, 4);                                   \
        E += __shfl_xor_sync(0xffffffffu, E, 8);                                   \
        E += __shfl_xor_sync(0xffffffffu, E, 16);                                  \
        float e = __expf(E);                                                       \
        float fA = __shfl_xor_sync(0xffffffffu, e, 1);                             \
        float fB = __shfl_xor_sync(0xffffffffu, e, 2);                             \
        float fC = __shfl_xor_sync(0xffffffffu, fA, 2);                            \
        accS += e;                                                                 \
        a0.x += e  * xv.x; a0.y += e  * xv.y; a0.z += e  * xv.z; a0.w += e  * xv.w;\
        a1.x += fA * xv.x; a1.y += fA * xv.y; a1.z += fA * xv.z; a1.w += fA * xv.w;\
        a2.x += fB * xv.x; a2.y += fB * xv.y; a2.z += fB * xv.z; a2.w += fB * xv.w;\
        a3.x += fC * xv.x; a3.y += fC * xv.y; a3.z += fC * xv.z; a3.w += fC * xv.w;\
    }

__global__ __launch_bounds__(256) void att_kernel(
    const float4* __restrict__ x,        // [N, 32] float4 view of [N,128]
    const float4* __restrict__ w,        // [4, 32]
    const void*   __restrict__ batch,
    float* __restrict__ out, int N)
{
    const int lane = threadIdx.x & 31;
    const int wid  = threadIdx.x >> 5;
    const int gw   = blockIdx.x * WARPS_PER_BLK + wid;
    const int is64 = g_is64;

    const int b1v = (lane >> 1) & 1;
    const int c   = 2 * (lane & 1) + b1v;       // head class of this lane
    const int h0 = c, h1 = c ^ 2, h2 = c ^ 1, h3 = c ^ 3;

    const int beg = gw * ROWS_PER_WARP;
    const int cnt = (beg < N) ? min(ROWS_PER_WARP, N - beg) : 0;

    if (cnt > 0) {
        // weights: lane l holds columns 4l..4l+3 per head
        float4 wv0 = w[0 * 32 + lane];
        float4 wv1 = w[1 * 32 + lane];
        float4 wv2 = w[2 * 32 + lane];
        float4 wv3 = w[3 * 32 + lane];

        // one coalesced load of this warp's whole batch slice
        int idx = beg + (lane < cnt ? lane : cnt - 1);
        int seg_l;
        if (is64) seg_l = (int)((const long long*)batch)[idx] & (NSEG - 1);
        else      seg_l = ((const int*)batch)[idx] & (NSEG - 1);

        int prev = __shfl_up_sync(0xffffffffu, seg_l, 1);
        unsigned diff = __ballot_sync(0xffffffffu, (lane == 0) || (seg_l != prev));

        int pos = 0;
        while (pos < cnt) {
            const int curseg = __shfl_sync(0xffffffffu, seg_l, pos);
            unsigned hi = (pos < 31) ? (diff & (0xFFFFFFFEu << pos)) : 0u;
            int nxt = hi ? (__ffs(hi) - 1) : cnt;
            if (nxt > cnt) nxt = cnt;

            float  accS = 0.0f;
            float4 a0 = make_float4(0,0,0,0), a1 = a0, a2 = a0, a3 = a0;

            // branch-free run [beg+pos, beg+nxt), 2-row unrolled for MLP
            int n = beg + pos;
            const int n_end = beg + nxt;
            for (; n + 1 < n_end; n += 2) {
                float4 xa = x[(n    ) * 32 + lane];
                float4 xb = x[(n + 1) * 32 + lane];
                ROW_BODY(xa, accS, a0, a1, a2, a3);
                ROW_BODY(xb, accS, a0, a1, a2, a3);
            }
            if (n < n_end) {
                float4 xa = x[n * 32 + lane];
                ROW_BODY(xa, accS, a0, a1, a2, a3);
            }

            // flush this run
            if (lane < 4) atomicAdd(&g_s[curseg * NHEAD + c], accS);
            float* base = &g_acc[curseg * NHEAD * EDIM + lane * 4];
            atomicAdd(base + h0 * EDIM + 0, a0.x);
            atomicAdd(base + h0 * EDIM + 1, a0.y);
            atomicAdd(base + h0 * EDIM + 2, a0.z);
            atomicAdd(base + h0 * EDIM + 3, a0.w);
            atomicAdd(base + h1 * EDIM + 0, a1.x);
            atomicAdd(base + h1 * EDIM + 1, a1.y);
            atomicAdd(base + h1 * EDIM + 2, a1.z);
            atomicAdd(base + h1 * EDIM + 3, a1.w);
            atomicAdd(base + h2 * EDIM + 0, a2.x);
            atomicAdd(base + h2 * EDIM + 1, a2.y);
            atomicAdd(base + h2 * EDIM + 2, a2.z);
            atomicAdd(base + h2 * EDIM + 3, a2.w);
            atomicAdd(base + h3 * EDIM + 0, a3.x);
            atomicAdd(base + h3 * EDIM + 1, a3.y);
            atomicAdd(base + h3 * EDIM + 2, a3.z);
            atomicAdd(base + h3 * EDIM + 3, a3.w);

            pos = nxt;
        }
    }

    // ---- inline finalize: last block to finish does the reduction ----
    __shared__ int s_last;
    __threadfence();
    __syncthreads();
    if (threadIdx.x == 0) {
        unsigned int prevd = atomicAdd(&g_done, 1u);
        s_last = (prevd == (unsigned int)(gridDim.x - 1)) ? 1 : 0;
    }
    __syncthreads();
    if (s_last) {
        for (int i = threadIdx.x; i < NSEG * EDIM; i += blockDim.x) {
            int b = i >> 7;
            int e = i & 127;
            float r = 0.0f;
#pragma unroll
            for (int h = 0; h < NHEAD; ++h) {
                float av = __ldcg(&g_acc[(b * NHEAD + h) * EDIM + e]);
                float sv = __ldcg(&g_s[b * NHEAD + h]);
                r += av / sv;
            }
            out[i] = r * (1.0f / NHEAD);
        }
    }
}

extern "C" void kernel_launch(void* const* d_in, const int* in_sizes, int n_in,
                              void* d_out, int out_size) {
    const float* x     = (const float*)d_in[0];
    const float* w     = (const float*)d_in[1];
    const void*  batch = d_in[2];

    int N = in_sizes[0] / EDIM;
    int nblk = (N + ROWS_PER_BLK - 1) / ROWS_PER_BLK;

    zero_kernel<<<(NSEG * NHEAD * EDIM + 255) / 256, 256>>>((const int*)batch, N);
    att_kernel<<<nblk, 256>>>((const float4*)x, (const float4*)w, batch,
                              (float*)d_out, N);
}